// round 17
// baseline (speedup 1.0000x reference)
#include <cuda_runtime.h>
#include <cuda_fp16.h>
#include <cstdint>

#define BS   8
#define SEQ  2048
#define DIM  512
#define MQ   128
#define NKK  64                 // keys per macro-iteration
#define DV   256
#define NQT  (SEQ/MQ)           // 16
#define NKT  (SEQ/NKK)          // 32

__device__ __half g_Qh[(size_t)BS*SEQ*DIM];
__device__ __half g_Kh[(size_t)BS*SEQ*DIM];
__device__ __half g_Vh[(size_t)BS*SEQ*DIM];

#define SM_Q   0
#define SM_K   131072
#define KBUF   32768            // keys 0-31 half / keys 32-63 half
#define SM_V   (131072 + 65536)
#define VBUF   16384
#define P_BUF  (SM_K + 57344)   // last 8 KB of K half-2 (d 384-511, keys 32-63)
#define L_BUF  (SM_V + 2*VBUF)  // 512 B row-sum exchange
#define SM_TOTAL (L_BUF + 512)  // 229888

__device__ __forceinline__ uint32_t smem_u32(const void* p) {
    uint32_t a;
    asm("{ .reg .u64 t; cvta.to.shared.u64 t, %1; cvt.u32.u64 %0, t; }" : "=r"(a) : "l"(p));
    return a;
}
// K-major SW128 blocked atoms: atom = 8 rows x 64 halfs (1024B).
__device__ __forceinline__ uint32_t km_off(int row, int col, int natomrows) {
    uint32_t off = ((uint32_t)((col >> 6) * natomrows + (row >> 3)) << 10)
                 + ((uint32_t)(row & 7) << 7) + ((uint32_t)(col & 63) << 1);
    return off ^ ((off >> 3) & 0x70u);
}
// P tile [128 rows x 32 keys] f16, 64B rows, XOR swizzle -> conflict-free
// for both accumulator-layout STS and ldsm A-frag reads.
__device__ __forceinline__ uint32_t poff(int r, int k) {
    return (uint32_t)(r * 64) + (((uint32_t)(k * 2)) ^ ((uint32_t)((r >> 1) & 3) << 4));
}
__device__ __forceinline__ uint32_t h2exp2(uint32_t x) {
    uint32_t y;
    asm("ex2.approx.f16x2 %0, %1;" : "=r"(y) : "r"(x));
    return y;
}
__device__ __forceinline__ void cp16(uint32_t dst, const void* src) {
    asm volatile("cp.async.cg.shared.global [%0], [%1], 16;" :: "r"(dst), "l"(src));
}
#define CP_COMMIT() asm volatile("cp.async.commit_group;" ::: "memory")
#define CP_WAIT1()  asm volatile("cp.async.wait_group 1;" ::: "memory")
#define CP_WAIT0()  asm volatile("cp.async.wait_group 0;" ::: "memory")
#define STS32(a, v) asm volatile("st.shared.b32 [%0], %1;" :: "r"(a), "r"(v) : "memory")

__device__ __forceinline__ void ldsm_x4(uint32_t* r, uint32_t addr) {
    asm volatile("ldmatrix.sync.aligned.m8n8.x4.shared.b16 {%0,%1,%2,%3}, [%4];"
        : "=r"(r[0]), "=r"(r[1]), "=r"(r[2]), "=r"(r[3]) : "r"(addr));
}
__device__ __forceinline__ void ldsm_x4t(uint32_t* r, uint32_t addr) {
    asm volatile("ldmatrix.sync.aligned.m8n8.x4.trans.shared.b16 {%0,%1,%2,%3}, [%4];"
        : "=r"(r[0]), "=r"(r[1]), "=r"(r[2]), "=r"(r[3]) : "r"(addr));
}
__device__ __forceinline__ void mma16816(float* c, const uint32_t* a, const uint32_t* b) {
    asm volatile("mma.sync.aligned.m16n8k16.row.col.f32.f16.f16.f32 "
        "{%0,%1,%2,%3}, {%4,%5,%6,%7}, {%8,%9}, {%0,%1,%2,%3};"
        : "+f"(c[0]), "+f"(c[1]), "+f"(c[2]), "+f"(c[3])
        : "r"(a[0]), "r"(a[1]), "r"(a[2]), "r"(a[3]), "r"(b[0]), "r"(b[1]));
}

__device__ __forceinline__ uint2 pack4(float4 a) {
    __half2 h;
    uint2 u;
    h = __floats2half2_rn(a.x, a.y); u.x = *reinterpret_cast<uint32_t*>(&h);
    h = __floats2half2_rn(a.z, a.w); u.y = *reinterpret_cast<uint32_t*>(&h);
    return u;
}
__global__ void convert_kernel(const float* __restrict__ q, const float* __restrict__ k,
                               const float* __restrict__ v, int half4) {
    int i = blockIdx.x * blockDim.x + threadIdx.x;
    if (i >= half4) return;
    int j = i + half4;
    const float4* q4 = reinterpret_cast<const float4*>(q);
    const float4* k4 = reinterpret_cast<const float4*>(k);
    const float4* v4 = reinterpret_cast<const float4*>(v);
    float4 qa = q4[i], ka = k4[i], va = v4[i];
    float4 qb = q4[j], kb = k4[j], vb = v4[j];
    uint2* qo = reinterpret_cast<uint2*>(g_Qh);
    uint2* ko = reinterpret_cast<uint2*>(g_Kh);
    uint2* vo = reinterpret_cast<uint2*>(g_Vh);
    qo[i] = pack4(qa); ko[i] = pack4(ka); vo[i] = pack4(va);
    qo[j] = pack4(qb); ko[j] = pack4(kb); vo[j] = pack4(vb);
}

// K main = everything except (keys>=32 && d>=384) [that 8 KB is the P region]
__device__ __forceinline__ void load_k_main(const __half* Kg, int tid, uint32_t kbuf) {
    #pragma unroll
    for (int i = tid; i < NKK * (DIM / 8); i += 256) {
        int r = i >> 6, c8 = i & 63;
        if (r < 32 || c8 < 48)
            cp16(kbuf + (r >= 32 ? KBUF : 0) + km_off(r & 31, c8 * 8, 4),
                 Kg + (size_t)r * DIM + c8 * 8);
    }
}
__device__ __forceinline__ void load_k_tail(const __half* Kg, int tid, uint32_t kbuf) {
    #pragma unroll
    for (int i = tid; i < 512; i += 256) {          // 8 KB: keys 32-63, d 384-511
        int r = 32 + (i >> 4), c8 = 48 + (i & 15);
        cp16(kbuf + KBUF + km_off(r & 31, c8 * 8, 4), Kg + (size_t)r * DIM + c8 * 8);
    }
}
__device__ __forceinline__ void load_v64(const __half* Vg, int tid, uint32_t vbuf) {
    #pragma unroll
    for (int i = tid; i < NKK * (DV / 8); i += 256) {
        int r = i >> 5, c8 = i & 31;
        cp16(vbuf + (r >= 32 ? VBUF : 0) + km_off(r & 31, c8 * 8, 4),
             Vg + (size_t)r * DIM + c8 * 8);
    }
}
__device__ __forceinline__ void load_q(const __half* Qg, int tid, uint32_t qbuf) {
    #pragma unroll 8
    for (int i = tid; i < MQ * (DIM / 8); i += 256) {
        int r = i >> 6, c8 = i & 63;
        cp16(qbuf + km_off(r, c8 * 8, 16), Qg + (size_t)r * DIM + c8 * 8);
    }
}

// FlashAttention (no-max softmax; l via ones-MMA). QK: 8 warps m-split
// (unchanged). PV: P exchanged through an 8 KB smem buffer (two 32-key
// phases) so warps re-partition O as 64x64 blocks -> V-frag traffic /4.
__global__ void __launch_bounds__(256, 1)
attn_kernel(const int* __restrict__ um_p, const int* __restrict__ cd_p,
            float* __restrict__ out) {
    extern __shared__ char smem[];
    const uint32_t sb = smem_u32(smem);
    float* lbuf = reinterpret_cast<float*>(smem + L_BUF);
    const int tid = threadIdx.x, lane = tid & 31, w = tid >> 5;
    const int g = blockIdx.x >> 4;
    const int inner = blockIdx.x & 15;
    const int b = inner >> 1, ds = inner & 1;
    const int dofs = ds * DV;
    const int um = um_p[0];
    const float cl2 = 1.4426950408889634f * rsqrtf((float)cd_p[0]);
    const float NEG = __int_as_float(0xff800000);
    const int nphase = (g >= 2) ? 2 : 1;
    const uint32_t ONES2[2] = {0x3C003C00u, 0x3C003C00u};

    const __half* Kg0 = g_Kh + ((size_t)(b * SEQ)) * DIM;
    const __half* Vg0 = g_Vh + ((size_t)(b * SEQ)) * DIM + dofs;

    // S-role (QK/softmax) indices
    const int arow = w * 16 + (lane & 15);
    const int acol = (lane >> 4) << 3;
    const int brow = lane & 7;
    const int bcol = ((lane >> 3) & 3) << 3;
    const int cofs = (lane & 3) << 1;
    // PV-role: warp owns O[64 rows x 64 cols]
    const int wr = w >> 2, wc = w & 3;
    const int vrow = lane & 15;
    const int vcol = (lane >> 4) << 3;
    const int prow = wr * 64 + (lane & 15);
    const int pcol = (lane >> 4) << 3;

    #pragma unroll 1
    for (int ph = 0; ph < nphase; ph++) {
        const int qi = ph ? (g - 2) : (NQT - 1) - g;
        const int q0 = qi * MQ;
        const int nkt = um ? (2 * qi + 2) : NKT;

        if (ph == 0) {
            load_q(g_Qh + ((size_t)(b * SEQ + q0)) * DIM, tid, sb + SM_Q);
            load_k_main(Kg0, tid, sb + SM_K);
            CP_COMMIT();                               // G_a: [Q, K_main(0)]
            load_v64(Vg0, tid, sb + SM_V);
            load_k_tail(Kg0, tid, sb + SM_K);
            CP_COMMIT();                               // G_b: [V(0), K_tail(0)]
        }

        float o[32][4];
        #pragma unroll
        for (int j = 0; j < 32; j++) { o[j][0] = 0.f; o[j][1] = 0.f; o[j][2] = 0.f; o[j][3] = 0.f; }
        float ol[4] = {0.f, 0.f, 0.f, 0.f};

        const int qrow0 = q0 + w * 16 + (lane >> 2);   // S-role rows (mask)
        const int qrow1 = qrow0 + 8;

        #pragma unroll 1
        for (int kt = 0; kt < nkt; kt++) {
            const int k0 = kt * NKK;
            const bool last = (kt + 1 == nkt);

            CP_WAIT1();            // [Q,K_main(kt)] in; [V,K_tail] may be in flight
            __syncthreads();

            float s[8][4];
            #pragma unroll
            for (int nt = 0; nt < 8; nt++) { s[nt][0] = 0.f; s[nt][1] = 0.f; s[nt][2] = 0.f; s[nt][3] = 0.f; }

            // ---- QK part1: kc2 0-11, all nt ----
            {
                uint32_t a0[4], a1[4], bb[2][4];
                ldsm_x4(bb[0], sb + SM_K + km_off(brow, bcol, 4));
                #pragma unroll
                for (int kc2 = 0; kc2 < 12; kc2++) {
                    ldsm_x4(a0, sb + SM_Q + km_off(arow, kc2 * 32 + acol, 16));
                    ldsm_x4(a1, sb + SM_Q + km_off(arow, kc2 * 32 + 16 + acol, 16));
                    #pragma unroll
                    for (int nt = 0; nt < 8; nt++) {
                        const int ib = kc2 * 8 + nt;
                        if (ib < 95) {
                            const int nn = ib + 1, nkc2 = nn >> 3, nnt = nn & 7;
                            ldsm_x4(bb[nn & 1], sb + SM_K + (nnt >= 4 ? KBUF : 0)
                                    + km_off((nnt & 3) * 8 + brow, nkc2 * 32 + bcol, 4));
                        }
                        mma16816(s[nt], a0, bb[ib & 1]);
                        mma16816(s[nt], a1, bb[ib & 1] + 2);
                    }
                }
            }
            // ---- QK part2: kc2 12-15, nt 0-3 (keys 0-31, not in tail) ----
            {
                uint32_t a0[4], a1[4], bb[2][4];
                ldsm_x4(bb[0], sb + SM_K + km_off(brow, 12 * 32 + bcol, 4));
                #pragma unroll
                for (int kc2 = 12; kc2 < 16; kc2++) {
                    ldsm_x4(a0, sb + SM_Q + km_off(arow, kc2 * 32 + acol, 16));
                    ldsm_x4(a1, sb + SM_Q + km_off(arow, kc2 * 32 + 16 + acol, 16));
                    #pragma unroll
                    for (int nt = 0; nt < 4; nt++) {
                        const int j = (kc2 - 12) * 4 + nt;
                        if (j < 15) {
                            const int nn = j + 1, nkc2 = 12 + (nn >> 2), nnt = nn & 3;
                            ldsm_x4(bb[nn & 1], sb + SM_K
                                    + km_off(nnt * 8 + brow, nkc2 * 32 + bcol, 4));
                        }
                        mma16816(s[nt], a0, bb[j & 1]);
                        mma16816(s[nt], a1, bb[j & 1] + 2);
                    }
                }
            }

            CP_WAIT0();            // V(kt) + K_tail(kt) landed
            __syncthreads();

            // ---- QK part3: kc2 12-15, nt 4-7 (the tail region) ----
            {
                uint32_t a0[4], a1[4], bb[2][4];
                ldsm_x4(bb[0], sb + SM_K + KBUF + km_off(brow, 12 * 32 + bcol, 4));
                #pragma unroll
                for (int kc2 = 12; kc2 < 16; kc2++) {
                    ldsm_x4(a0, sb + SM_Q + km_off(arow, kc2 * 32 + acol, 16));
                    ldsm_x4(a1, sb + SM_Q + km_off(arow, kc2 * 32 + 16 + acol, 16));
                    #pragma unroll
                    for (int nt = 4; nt < 8; nt++) {
                        const int j = (kc2 - 12) * 4 + (nt - 4);
                        if (j < 15) {
                            const int nn = j + 1, nkc2 = 12 + (nn >> 2), nnt = 4 + (nn & 3);
                            ldsm_x4(bb[nn & 1], sb + SM_K + KBUF
                                    + km_off((nnt & 3) * 8 + brow, nkc2 * 32 + bcol, 4));
                        }
                        mma16816(s[nt], a0, bb[j & 1]);
                        mma16816(s[nt], a1, bb[j & 1] + 2);
                    }
                }
            }
            __syncthreads();       // all K reads done
            if (!last) {
                load_k_main(Kg0 + (size_t)(k0 + NKK) * DIM, tid, sb + SM_K);
            } else if (ph + 1 < nphase) {
                load_q(g_Qh + ((size_t)(b * SEQ + (g - 2) * MQ)) * DIM, tid, sb + SM_Q);
                load_k_main(Kg0, tid, sb + SM_K);
            }
            CP_COMMIT();           // G_a

            // ---- causal mask ----
            if (um && kt >= 2 * qi) {
                #pragma unroll
                for (int nt = 0; nt < 8; nt++) {
                    int c = k0 + nt * 8 + cofs;
                    if (c     > qrow0) s[nt][0] = NEG;
                    if (c + 1 > qrow0) s[nt][1] = NEG;
                    if (c     > qrow1) s[nt][2] = NEG;
                    if (c + 1 > qrow1) s[nt][3] = NEG;
                }
            }

            // ---- exp + pack + l-MMA ----
            uint32_t pa[4][4];
            #pragma unroll
            for (int q = 0; q < 4; q++) {
                #pragma unroll
                for (int j = 0; j < 2; j++) {
                    const int nt = 2 * q + j;
                    __half2 hh01 = __floats2half2_rn(s[nt][0] * cl2, s[nt][1] * cl2);
                    __half2 hh23 = __floats2half2_rn(s[nt][2] * cl2, s[nt][3] * cl2);
                    pa[q][2*j]     = h2exp2(*reinterpret_cast<uint32_t*>(&hh01));
                    pa[q][2*j + 1] = h2exp2(*reinterpret_cast<uint32_t*>(&hh23));
                }
                mma16816(ol, pa[q], ONES2);
            }

            // ---- two PV phases: STS P, sync, PV(64x64 blocks) ----
            const int pr0 = w * 16 + (lane >> 2);
            #pragma unroll
            for (int hph = 0; hph < 2; hph++) {
                #pragma unroll
                for (int qq = 0; qq < 2; qq++) {
                    const int q = hph * 2 + qq;
                    #pragma unroll
                    for (int j = 0; j < 2; j++) {
                        const int kb = (qq * 2 + j) * 8 + cofs;   // local key 0-31
                        STS32(sb + P_BUF + poff(pr0,     kb), pa[q][2*j]);
                        STS32(sb + P_BUF + poff(pr0 + 8, kb), pa[q][2*j + 1]);
                    }
                }
                __syncthreads();   // P phase visible
                #pragma unroll
                for (int kc = 0; kc < 2; kc++) {
                    uint32_t aP[4][4];
                    #pragma unroll
                    for (int mt = 0; mt < 4; mt++)
                        ldsm_x4(aP[mt], sb + P_BUF + poff(prow + mt * 16 - (lane & 15) + (lane & 15), kc * 16 + pcol));
                    #pragma unroll
                    for (int dt2 = 0; dt2 < 4; dt2++) {
                        uint32_t bb[4];
                        ldsm_x4t(bb, sb + SM_V + hph * VBUF
                                 + km_off(kc * 16 + vrow, wc * 64 + dt2 * 16 + vcol, 4));
                        #pragma unroll
                        for (int mt = 0; mt < 4; mt++) {
                            mma16816(o[(mt * 4 + dt2) * 2],     aP[mt], bb);
                            mma16816(o[(mt * 4 + dt2) * 2 + 1], aP[mt], bb + 2);
                        }
                    }
                }
                __syncthreads();   // P consumed (next phase overwrites) / V read done
            }

            if (!last) {
                load_v64(Vg0 + (size_t)(k0 + NKK) * DIM, tid, sb + SM_V);
                load_k_tail(Kg0 + (size_t)(k0 + NKK) * DIM, tid, sb + SM_K);
            } else if (ph + 1 < nphase) {
                load_v64(Vg0, tid, sb + SM_V);
                load_k_tail(Kg0, tid, sb + SM_K);
            }
            CP_COMMIT();           // G_b
        }

        // ---- epilogue: exchange l, divide, store ----
        if ((lane & 3) == 0) {
            lbuf[w * 16 + (lane >> 2)]     = ol[0];
            lbuf[w * 16 + 8 + (lane >> 2)] = ol[2];
        }
        __syncthreads();
        #pragma unroll
        for (int mt = 0; mt < 4; mt++) {
            const int rA = wr * 64 + mt * 16 + (lane >> 2);
            const int rB = rA + 8;
            const float iA = 1.f / lbuf[rA];
            const float iB = 1.f / lbuf[rB];
            float* outA = out + ((size_t)b * SEQ + q0 + rA) * DIM + dofs + wc * 64;
            float* outB = out + ((size_t)b * SEQ + q0 + rB) * DIM + dofs + wc * 64;
            #pragma unroll
            for (int dt2 = 0; dt2 < 4; dt2++) {
                #pragma unroll
                for (int nn = 0; nn < 2; nn++) {
                    const int idx = (mt * 4 + dt2) * 2 + nn;
                    const int col = dt2 * 16 + nn * 8 + cofs;
                    *reinterpret_cast<float2*>(outA + col) =
                        make_float2(o[idx][0] * iA, o[idx][1] * iA);
                    *reinterpret_cast<float2*>(outB + col) =
                        make_float2(o[idx][2] * iB, o[idx][3] * iB);
                }
            }
        }
        __syncthreads();   // lbuf reused next phase
    }
}

extern "C" void kernel_launch(void* const* d_in, const int* in_sizes, int n_in,
                              void* d_out, int out_size) {
    const float* Q = (const float*)d_in[0];
    const float* K = (const float*)d_in[1];
    const float* V = (const float*)d_in[2];
    const int* use_mask = (const int*)d_in[3];
    const int* cell_dim = (const int*)d_in[4];
    float* out = (float*)d_out;

    int half4 = (BS * SEQ * DIM) / 8;
    convert_kernel<<<(half4 + 255) / 256, 256>>>(Q, K, V, half4);

    cudaFuncSetAttribute(attn_kernel, cudaFuncAttributeMaxDynamicSharedMemorySize, SM_TOTAL);
    attn_kernel<<<9 * 16, 256, SM_TOTAL>>>(use_mask, cell_dim, out);
}